// round 11
// baseline (speedup 1.0000x reference)
#include <cuda_runtime.h>

#define NN 256
#define TT 1500
#define R 4
#define CT (32 * R)                  // 128 steps per warp-chunk
#define NFULL (TT / CT)              // 11 full chunks
#define PLANE (NN * TT)              // 384000 floats

// q[s][n][t] = 0.3125 - 0.075*g_max[s][n]*sat(u_s[n][t]); a_ij(t) = q0+q1
__device__ __align__(16) float g_q[2][PLANE];

__global__ __launch_bounds__(256) void prep_kernel(const float* __restrict__ u0,
                                                   const float* __restrict__ u1,
                                                   const float* __restrict__ ksyn) {
    int g = blockIdx.x * 256 + threadIdx.x;      // float4 index
    if (g >= PLANE / 4) return;
    int n = (g * 4) / TT;                        // TT%4==0 -> same row

    float k0 = ksyn[n];
    float c0 = 0.075f * k0 / (20.0f - 2.0f * k0);
    float4 a = ((const float4*)u0)[g];
    float4 r0;
    r0.x = fmaf(-c0, __saturatef(a.x), 0.3125f);
    r0.y = fmaf(-c0, __saturatef(a.y), 0.3125f);
    r0.z = fmaf(-c0, __saturatef(a.z), 0.3125f);
    r0.w = fmaf(-c0, __saturatef(a.w), 0.3125f);
    ((float4*)g_q[0])[g] = r0;

    float k1 = ksyn[NN + n];
    float c1 = 0.075f * k1 / (20.0f - 2.0f * k1);
    float4 b = ((const float4*)u1)[g];
    float4 r1;
    r1.x = fmaf(-c1, __saturatef(b.x), 0.3125f);
    r1.y = fmaf(-c1, __saturatef(b.y), 0.3125f);
    r1.z = fmaf(-c1, __saturatef(b.z), 0.3125f);
    r1.w = fmaf(-c1, __saturatef(b.w), 0.3125f);
    ((float4*)g_q[1])[g] = r1;
}

// One cell's 128-step chunk, 6 shfl. Carry-baked truncated scan (window
// 8 lanes = 32 steps; dropped terms <= 0.625^32 ~ 3e-7); final rotate shfl
// hands lanes 1..31 their v_start and lane 0 the next carry in one op.
template<bool TAIL>
__device__ __forceinline__ void cell_chunk(const float4 x, const float4 y,
                                           const bool act, const int lane,
                                           float& carry, float* __restrict__ o,
                                           const int t) {
    float a0, a1, a2, a3, A, B;
    if (!TAIL || act) {
        a0 = x.x + y.x;  a1 = x.y + y.y;  a2 = x.z + y.z;  a3 = x.w + y.w;
        A = a0; B = fmaf(-20.0f, a0, 12.5f);
        B = fmaf(a1, B, fmaf(-20.0f, a1, 12.5f)); A *= a1;
        B = fmaf(a2, B, fmaf(-20.0f, a2, 12.5f)); A *= a2;
        B = fmaf(a3, B, fmaf(-20.0f, a3, 12.5f)); A *= a3;
    } else {
        A = 1.0f; B = 0.0f;
        a0 = a1 = a2 = a3 = 1.0f;
    }

    if (lane == 0) B = fmaf(A, carry, B);        // bake carry into lane 0

    float Au, Bu;
    Au = __shfl_up_sync(0xffffffffu, A, 1);
    Bu = __shfl_up_sync(0xffffffffu, B, 1);
    if (lane >= 1) { B = fmaf(A, Bu, B); A *= Au; }
    Au = __shfl_up_sync(0xffffffffu, A, 2);
    Bu = __shfl_up_sync(0xffffffffu, B, 2);
    if (lane >= 2) { B = fmaf(A, Bu, B); A *= Au; }
    Bu = __shfl_up_sync(0xffffffffu, B, 4);
    if (lane >= 4) { B = fmaf(A, Bu, B); }

    float rot = __shfl_sync(0xffffffffu, B, (lane + 31) & 31);
    float v;
    if (lane == 0) { v = carry; carry = rot; }   // rot == B_31 == next carry
    else           { v = rot; }

    if (!TAIL || act) {
        float4 r;
        v = fmaf(a0, v, fmaf(-20.0f, a0, 12.5f)); r.x = v;
        v = fmaf(a1, v, fmaf(-20.0f, a1, 12.5f)); r.y = v;
        v = fmaf(a2, v, fmaf(-20.0f, a2, 12.5f)); r.z = v;
        v = fmaf(a3, v, fmaf(-20.0f, a3, 12.5f)); r.w = v;
        *(float4*)(o + t) = r;
    }
}

// Warp owns a 2x2 cell tile; all addresses from 3 base pointers with
// compile-time offsets (TT, PLANE fit LDG/STG imm24) to cap registers.
__global__ __launch_bounds__(256, 6) void sim_kernel(float* __restrict__ out) {
    const int lane = threadIdx.x & 31;
    const int w    = threadIdx.x >> 5;              // 0..7
    const int i0 = blockIdx.y * 4 + (w >> 2) * 2;
    const int j0 = blockIdx.x * 8 + (w & 3) * 2;

    const float* __restrict__ qi = g_q[0] + i0 * TT;
    const float* __restrict__ qj = g_q[1] + j0 * TT;
    float* __restrict__ ob = out + (i0 * NN + j0) * TT;

    float c00 = 0.0f, c01 = 0.0f, c10 = 0.0f, c11 = 0.0f;

    #pragma unroll 1
    for (int c = 0; c < NFULL; c++) {
        const int t = c * CT + lane * R;

        float4 x0 = *(const float4*)(qi + t);
        float4 x1 = *(const float4*)(qi + t + TT);
        float4 y0 = *(const float4*)(qj + t);
        float4 y1 = *(const float4*)(qj + t + TT);

        cell_chunk<false>(x0, y0, true, lane, c00, ob + t,              0);
        cell_chunk<false>(x0, y1, true, lane, c01, ob + t + TT,         0);
        cell_chunk<false>(x1, y0, true, lane, c10, ob + t + PLANE,      0);
        cell_chunk<false>(x1, y1, true, lane, c11, ob + t + PLANE + TT, 0);
    }

    // tail chunk: steps 1408..1499, lanes 0..22 active (whole float4s)
    {
        const int t = NFULL * CT + lane * R;
        const bool act = (t < TT);

        float4 x0, x1, y0, y1;
        if (act) {
            x0 = *(const float4*)(qi + t);
            x1 = *(const float4*)(qi + t + TT);
            y0 = *(const float4*)(qj + t);
            y1 = *(const float4*)(qj + t + TT);
        }

        cell_chunk<true>(x0, y0, act, lane, c00, ob + t,              0);
        cell_chunk<true>(x0, y1, act, lane, c01, ob + t + TT,         0);
        cell_chunk<true>(x1, y0, act, lane, c10, ob + t + PLANE,      0);
        cell_chunk<true>(x1, y1, act, lane, c11, ob + t + PLANE + TT, 0);
    }
}

extern "C" void kernel_launch(void* const* d_in, const int* in_sizes, int n_in,
                              void* d_out, int out_size) {
    const float* u0   = (const float*)d_in[0];   // u_pre_0 (N,T)
    const float* u1   = (const float*)d_in[1];   // u_pre_1 (N,T)
    const float* ksyn = (const float*)d_in[2];   // k_syn (2,N)
    float* out = (float*)d_out;                  // (N,N,T) fp32

    prep_kernel<<<(PLANE / 4 + 255) / 256, 256>>>(u0, u1, ksyn);

    dim3 grid(NN / 8, NN / 4);                   // 32 x 64 = 2048 blocks
    sim_kernel<<<grid, 256>>>(out);
}

// round 12
// speedup vs baseline: 1.2759x; 1.2759x over previous
#include <cuda_runtime.h>

#define NN 256
#define TT 1500
#define R 4
#define CT (32 * R)                  // 128 steps per warp-chunk
#define NFULL (TT / CT)              // 11 full chunks (tail: 92 steps, lanes 0..22)

// One cell's 128-step chunk, 6 shfl. Carry-baked truncated scan (window
// 8 lanes = 32 steps; dropped terms <= 0.625^32 ~ 3e-7); final rotate shfl
// hands lanes 1..31 their v_start and lane 0 the next carry in one op.
// x, y are the precomputed half-coefficients: a_t = x_t + y_t.
template<bool TAIL>
__device__ __forceinline__ void cell_chunk(const float4 x, const float4 y,
                                           const bool act, const int lane,
                                           float& carry, float* __restrict__ o) {
    float a0, a1, a2, a3, A, B;
    if (!TAIL || act) {
        a0 = x.x + y.x;  a1 = x.y + y.y;  a2 = x.z + y.z;  a3 = x.w + y.w;
        A = a0; B = fmaf(-20.0f, a0, 12.5f);
        B = fmaf(a1, B, fmaf(-20.0f, a1, 12.5f)); A *= a1;
        B = fmaf(a2, B, fmaf(-20.0f, a2, 12.5f)); A *= a2;
        B = fmaf(a3, B, fmaf(-20.0f, a3, 12.5f)); A *= a3;
    } else {
        A = 1.0f; B = 0.0f;
        a0 = a1 = a2 = a3 = 1.0f;
    }

    if (lane == 0) B = fmaf(A, carry, B);        // bake carry into lane 0

    float Au, Bu;
    Au = __shfl_up_sync(0xffffffffu, A, 1);
    Bu = __shfl_up_sync(0xffffffffu, B, 1);
    if (lane >= 1) { B = fmaf(A, Bu, B); A *= Au; }
    Au = __shfl_up_sync(0xffffffffu, A, 2);
    Bu = __shfl_up_sync(0xffffffffu, B, 2);
    if (lane >= 2) { B = fmaf(A, Bu, B); A *= Au; }
    Bu = __shfl_up_sync(0xffffffffu, B, 4);
    if (lane >= 4) { B = fmaf(A, Bu, B); }

    float rot = __shfl_sync(0xffffffffu, B, (lane + 31) & 31);
    float v;
    if (lane == 0) { v = carry; carry = rot; }   // rot == B_31 == next carry
    else           { v = rot; }

    if (!TAIL || act) {
        float4 r;
        v = fmaf(a0, v, fmaf(-20.0f, a0, 12.5f)); r.x = v;
        v = fmaf(a1, v, fmaf(-20.0f, a1, 12.5f)); r.y = v;
        v = fmaf(a2, v, fmaf(-20.0f, a2, 12.5f)); r.z = v;
        v = fmaf(a3, v, fmaf(-20.0f, a3, 12.5f)); r.w = v;
        __stcs((float4*)o, r);                    // streaming: never re-read
    }
}

// load u row chunk -> half-coefficient q = 0.3125 - c*sat(u)
__device__ __forceinline__ float4 load_q(const float* __restrict__ base,
                                         const int t, const float c) {
    float4 x = *(const float4*)(base + t);
    float4 q;
    q.x = fmaf(-c, __saturatef(x.x), 0.3125f);
    q.y = fmaf(-c, __saturatef(x.y), 0.3125f);
    q.z = fmaf(-c, __saturatef(x.z), 0.3125f);
    q.w = fmaf(-c, __saturatef(x.w), 0.3125f);
    return q;
}

// Fully fused: warp owns a 2x2 cell tile, reads u directly (coefficients
// applied inline), 8 explicit pointers for max load MLP (R10 chassis).
__global__ __launch_bounds__(256, 4) void sim_kernel(
    const float* __restrict__ u0, const float* __restrict__ u1,
    const float* __restrict__ ksyn, float* __restrict__ out)
{
    const int lane = threadIdx.x & 31;
    const int w    = threadIdx.x >> 5;              // 0..7
    const int i0 = blockIdx.y * 4 + (w >> 2) * 2;
    const int j0 = blockIdx.x * 8 + (w & 3) * 2;

    const float ki0 = ksyn[i0],      ki1 = ksyn[i0 + 1];
    const float kj0 = ksyn[NN + j0], kj1 = ksyn[NN + j0 + 1];
    const float ci0 = 0.075f * ki0 / (20.0f - 2.0f * ki0);
    const float ci1 = 0.075f * ki1 / (20.0f - 2.0f * ki1);
    const float cj0 = 0.075f * kj0 / (20.0f - 2.0f * kj0);
    const float cj1 = 0.075f * kj1 / (20.0f - 2.0f * kj1);

    const float* __restrict__ xi0 = u0 + i0 * TT;
    const float* __restrict__ xi1 = xi0 + TT;
    const float* __restrict__ yj0 = u1 + j0 * TT;
    const float* __restrict__ yj1 = yj0 + TT;

    float* __restrict__ o00 = out + (i0 * NN + j0) * TT;
    float* __restrict__ o01 = o00 + TT;
    float* __restrict__ o10 = o00 + NN * TT;
    float* __restrict__ o11 = o10 + TT;

    float c00 = 0.0f, c01 = 0.0f, c10 = 0.0f, c11 = 0.0f;

    #pragma unroll 1
    for (int c = 0; c < NFULL; c++) {
        const int t = c * CT + lane * R;

        float4 qx0 = load_q(xi0, t, ci0);
        float4 qx1 = load_q(xi1, t, ci1);
        float4 qy0 = load_q(yj0, t, cj0);
        float4 qy1 = load_q(yj1, t, cj1);

        cell_chunk<false>(qx0, qy0, true, lane, c00, o00 + t);
        cell_chunk<false>(qx0, qy1, true, lane, c01, o01 + t);
        cell_chunk<false>(qx1, qy0, true, lane, c10, o10 + t);
        cell_chunk<false>(qx1, qy1, true, lane, c11, o11 + t);
    }

    // tail chunk: steps 1408..1499, lanes 0..22 active (whole float4s)
    {
        const int t = NFULL * CT + lane * R;
        const bool act = (t < TT);

        float4 qx0, qx1, qy0, qy1;
        if (act) {
            qx0 = load_q(xi0, t, ci0);
            qx1 = load_q(xi1, t, ci1);
            qy0 = load_q(yj0, t, cj0);
            qy1 = load_q(yj1, t, cj1);
        }

        cell_chunk<true>(qx0, qy0, act, lane, c00, o00 + t);
        cell_chunk<true>(qx0, qy1, act, lane, c01, o01 + t);
        cell_chunk<true>(qx1, qy0, act, lane, c10, o10 + t);
        cell_chunk<true>(qx1, qy1, act, lane, c11, o11 + t);
    }
}

extern "C" void kernel_launch(void* const* d_in, const int* in_sizes, int n_in,
                              void* d_out, int out_size) {
    const float* u0   = (const float*)d_in[0];   // u_pre_0 (N,T)
    const float* u1   = (const float*)d_in[1];   // u_pre_1 (N,T)
    const float* ksyn = (const float*)d_in[2];   // k_syn (2,N)
    float* out = (float*)d_out;                  // (N,N,T) fp32

    dim3 grid(NN / 8, NN / 4);                   // 32 x 64 = 2048 blocks
    sim_kernel<<<grid, 256>>>(u0, u1, ksyn, out);
}